// round 13
// baseline (speedup 1.0000x reference)
#include <cuda_runtime.h>
#include <cuda_bf16.h>
#include <stdint.h>

#define SQ 2048
#define DH 64
#define NH 16
#define NB 2
#define INV_T 0.125f
#define N_ELEM (NB * NH * SQ * DH)        // 4194304
#define N_ATTN ((size_t)NB * NH * SQ * SQ) // 134217728

__device__ float g_rowsum[NB * NH * SQ];
// pre-split bf16 hi/lo planes for Q/K/V
__device__ unsigned short gQh[N_ELEM], gQl[N_ELEM];
__device__ unsigned short gKh[N_ELEM], gKl[N_ELEM];
__device__ unsigned short gVh[N_ELEM], gVl[N_ELEM];
// p' planes (bf16 hi/lo)
__device__ unsigned short gPh[N_ATTN], gPl[N_ATTN];
// bit-packed mask: [B][S][64 words]
__device__ uint32_t g_mbits[NB * SQ * 64];

// ---------------- PTX helpers ----------------

__device__ __forceinline__ uint32_t smem_u32(const void* p) {
    return (uint32_t)__cvta_generic_to_shared(p);
}
__device__ __forceinline__ void ldsm_x4(uint32_t addr, uint32_t* r) {
    asm volatile("ldmatrix.sync.aligned.m8n8.x4.shared.b16 {%0,%1,%2,%3}, [%4];"
                 : "=r"(r[0]), "=r"(r[1]), "=r"(r[2]), "=r"(r[3]) : "r"(addr));
}
__device__ __forceinline__ void ldsm_x4t(uint32_t addr, uint32_t* r) {
    asm volatile("ldmatrix.sync.aligned.m8n8.x4.trans.shared.b16 {%0,%1,%2,%3}, [%4];"
                 : "=r"(r[0]), "=r"(r[1]), "=r"(r[2]), "=r"(r[3]) : "r"(addr));
}
__device__ __forceinline__ void mma_bf16(float* c, const uint32_t* a, const uint32_t* b) {
    asm volatile(
        "mma.sync.aligned.m16n8k16.row.col.f32.bf16.bf16.f32 "
        "{%0,%1,%2,%3}, {%4,%5,%6,%7}, {%8,%9}, {%0,%1,%2,%3};"
        : "+f"(c[0]), "+f"(c[1]), "+f"(c[2]), "+f"(c[3])
        : "r"(a[0]), "r"(a[1]), "r"(a[2]), "r"(a[3]), "r"(b[0]), "r"(b[1]));
}
__device__ __forceinline__ void cp16(uint32_t s, const void* g) {
    asm volatile("cp.async.cg.shared.global [%0], [%1], 16;" :: "r"(s), "l"(g));
}
#define CP_COMMIT asm volatile("cp.async.commit_group;")
#define CP_WAIT1  asm volatile("cp.async.wait_group 1;")
#define CP_WAIT0  asm volatile("cp.async.wait_group 0;")

__device__ __forceinline__ void split_bf(float x, uint16_t& h, uint16_t& l) {
    __nv_bfloat16 bh = __float2bfloat16(x);
    float r = x - __bfloat162float(bh);
    __nv_bfloat16 bl = __float2bfloat16(r);
    h = __bfloat16_as_ushort(bh);
    l = __bfloat16_as_ushort(bl);
}
__device__ __forceinline__ uint32_t pack2(uint16_t a, uint16_t b) {
    return (uint32_t)a | ((uint32_t)b << 16);
}
__device__ __forceinline__ float2 unpack2(uint32_t u) {
    __nv_bfloat162 b = *reinterpret_cast<__nv_bfloat162*>(&u);
    return __bfloat1622float2(b);
}

// ================= prep kernels =================

__global__ void __launch_bounds__(256)
prep(const float* __restrict__ q, const float* __restrict__ k, const float* __restrict__ v)
{
    int id = blockIdx.x * 256 + threadIdx.x;          // 0 .. 3*N/4-1
    int tsel = id / (N_ELEM / 4);
    int i4   = id % (N_ELEM / 4);
    const float* src = (tsel == 0) ? q : (tsel == 1) ? k : v;
    unsigned short* dh = (tsel == 0) ? gQh : (tsel == 1) ? gKh : gVh;
    unsigned short* dl = (tsel == 0) ? gQl : (tsel == 1) ? gKl : gVl;

    float4 f = ((const float4*)src)[i4];
    uint16_t h0, l0, h1, l1, h2, l2, h3, l3;
    split_bf(f.x, h0, l0); split_bf(f.y, h1, l1);
    split_bf(f.z, h2, l2); split_bf(f.w, h3, l3);
    uint2 H; H.x = pack2(h0, h1); H.y = pack2(h2, h3);
    uint2 L; L.x = pack2(l0, l1); L.y = pack2(l2, l3);
    ((uint2*)dh)[i4] = H;
    ((uint2*)dl)[i4] = L;
}

__global__ void __launch_bounds__(256)
prep_mask(const int* __restrict__ mask)
{
    int wid = blockIdx.x * 256 + threadIdx.x;         // word index 0..NB*SQ*64-1
    const int4* src = (const int4*)(mask + (size_t)wid * 32);
    uint32_t bits = 0;
    #pragma unroll
    for (int c = 0; c < 8; ++c) {
        int4 m = src[c];
        bits |= (m.x ? 1u : 0u) << (c * 4 + 0);
        bits |= (m.y ? 1u : 0u) << (c * 4 + 1);
        bits |= (m.z ? 1u : 0u) << (c * 4 + 2);
        bits |= (m.w ? 1u : 0u) << (c * 4 + 3);
    }
    g_mbits[wid] = bits;
}

// ================= Kernel 1: p' planes = split(exp(mask(QK^T/T))), row sums =================
// 64 q-rows/CTA, 256 thr (4 M x 2 N warps), j-tiles of 128, cp.async double-buffer.
#define PQ_B 144                               // 72 bf16 pitch (bytes)
#define K1_QH 0
#define K1_QL (64 * PQ_B)                      // 9216
#define K1_KBUF 18432                          // 2 buffers of (KH+KL) = 36864 each
#define K1_KSZ  36864
#define K1_SUM (K1_KBUF + 2 * K1_KSZ)          // 92160
#define K1_SMEM (K1_SUM + 256)

__global__ void __launch_bounds__(256, 2)
k1_qk()
{
    extern __shared__ char sm[];
    float* sSum = (float*)(sm + K1_SUM);

    const int t = threadIdx.x;
    const int lane = t & 31, w = t >> 5;
    const int g = lane >> 2, tg = lane & 3;
    const int wm = w >> 1, wn = w & 1;

    const int h  = blockIdx.y;
    const int b  = blockIdx.z;
    const int q0 = blockIdx.x * 64;
    const int bh = b * NH + h;

    const size_t qbase = ((size_t)bh * SQ + q0) * DH;   // ushort index
    const size_t kbase = (size_t)bh * SQ * DH;
    const size_t pbase = ((size_t)bh * SQ + q0) * SQ;

    // prologue: stage Q planes + K tile 0
    #pragma unroll
    for (int i = 0; i < 4; ++i) {
        int lin = i * 256 + t;
        int plane = lin >> 9, row = (lin >> 3) & 63, c = lin & 7;
        const unsigned short* src = (plane ? gQl : gQh) + qbase + (size_t)row * DH + c * 8;
        cp16(smem_u32(sm + (plane ? K1_QL : K1_QH) + row * PQ_B + c * 16), src);
    }
    #pragma unroll
    for (int i = 0; i < 8; ++i) {
        int lin = i * 256 + t;
        int plane = lin >> 10, row = (lin >> 3) & 127, c = lin & 7;
        const unsigned short* src = (plane ? gKl : gKh) + kbase + (size_t)row * DH + c * 8;
        cp16(smem_u32(sm + K1_KBUF + plane * (K1_KSZ / 2) + row * PQ_B + c * 16), src);
    }
    CP_COMMIT;
    if (t < 64) sSum[t] = 0.0f;

    const int aRow = wm * 16 + (lane & 15);
    const int aCol = ((lane >> 4) << 3);
    const int bRow = ((lane >> 4) << 3) + (lane & 7);
    const int bCol = ((lane >> 3) & 1) << 3;
    const int rl0 = wm * 16 + g, rl1 = rl0 + 8;
    float rs0 = 0.0f, rs1 = 0.0f;

    const uint32_t* mb0 = &g_mbits[((size_t)b * SQ + q0 + rl0) * 64];
    const uint32_t* mb1 = &g_mbits[((size_t)b * SQ + q0 + rl1) * 64];

    for (int jt = 0; jt < 16; ++jt) {
        __syncthreads();
        if (jt < 15) {
            char* kb = sm + K1_KBUF + ((jt + 1) & 1) * K1_KSZ;
            size_t kt = kbase + (size_t)(jt + 1) * 128 * DH;
            #pragma unroll
            for (int i = 0; i < 8; ++i) {
                int lin = i * 256 + t;
                int plane = lin >> 10, row = (lin >> 3) & 127, c = lin & 7;
                const unsigned short* src = (plane ? gKl : gKh) + kt + (size_t)row * DH + c * 8;
                cp16(smem_u32(kb + plane * (K1_KSZ / 2) + row * PQ_B + c * 16), src);
            }
            CP_COMMIT;
            CP_WAIT1;
        } else {
            CP_WAIT0;
        }
        __syncthreads();

        const char* KB = sm + K1_KBUF + (jt & 1) * K1_KSZ;

        float acc[8][4];
        #pragma unroll
        for (int nt = 0; nt < 8; ++nt)
            acc[nt][0] = acc[nt][1] = acc[nt][2] = acc[nt][3] = 0.0f;

        #pragma unroll
        for (int kc = 0; kc < 4; ++kc) {
            uint32_t Ah[4], Al[4];
            int aoff = aRow * PQ_B + (kc * 16 + aCol) * 2;
            ldsm_x4(smem_u32(sm + K1_QH + aoff), Ah);
            ldsm_x4(smem_u32(sm + K1_QL + aoff), Al);

            #pragma unroll
            for (int np = 0; np < 4; ++np) {
                uint32_t Bh[4], Bl[4];
                int boff = (wn * 64 + np * 16 + bRow) * PQ_B + (kc * 16 + bCol) * 2;
                ldsm_x4(smem_u32(KB + boff), Bh);
                ldsm_x4(smem_u32(KB + (K1_KSZ / 2) + boff), Bl);
                mma_bf16(acc[np * 2],     Ah, Bh);
                mma_bf16(acc[np * 2],     Ah, Bl);
                mma_bf16(acc[np * 2],     Al, Bh);
                mma_bf16(acc[np * 2 + 1], Ah, Bh + 2);
                mma_bf16(acc[np * 2 + 1], Ah, Bl + 2);
                mma_bf16(acc[np * 2 + 1], Al, Bh + 2);
            }
        }

        // epilogue: mask bits, exp, split, store p' planes, rowsums
        const uint2 mw0 = *(const uint2*)&mb0[jt * 4 + wn * 2];
        const uint2 mw1 = *(const uint2*)&mb1[jt * 4 + wn * 2];
        #pragma unroll
        for (int nt = 0; nt < 8; ++nt) {
            int sh = (nt & 3) * 8 + 2 * tg;
            uint32_t w0 = (nt < 4) ? mw0.x : mw0.y;
            uint32_t w1 = (nt < 4) ? mw1.x : mw1.y;
            float e00 = ((w0 >> sh) & 1)       ? __expf(acc[nt][0] * INV_T) : 0.0f;
            float e01 = ((w0 >> (sh + 1)) & 1) ? __expf(acc[nt][1] * INV_T) : 0.0f;
            float e10 = ((w1 >> sh) & 1)       ? __expf(acc[nt][2] * INV_T) : 0.0f;
            float e11 = ((w1 >> (sh + 1)) & 1) ? __expf(acc[nt][3] * INV_T) : 0.0f;
            rs0 += e00 + e01;
            rs1 += e10 + e11;

            int jc = jt * 128 + wn * 64 + nt * 8 + 2 * tg;
            uint16_t h0, l0, h1, l1;
            split_bf(e00, h0, l0); split_bf(e01, h1, l1);
            *(uint32_t*)&gPh[pbase + (size_t)rl0 * SQ + jc] = pack2(h0, h1);
            *(uint32_t*)&gPl[pbase + (size_t)rl0 * SQ + jc] = pack2(l0, l1);
            split_bf(e10, h0, l0); split_bf(e11, h1, l1);
            *(uint32_t*)&gPh[pbase + (size_t)rl1 * SQ + jc] = pack2(h0, h1);
            *(uint32_t*)&gPl[pbase + (size_t)rl1 * SQ + jc] = pack2(l0, l1);
        }
    }

    rs0 += __shfl_xor_sync(0xffffffffu, rs0, 1);
    rs0 += __shfl_xor_sync(0xffffffffu, rs0, 2);
    rs1 += __shfl_xor_sync(0xffffffffu, rs1, 1);
    rs1 += __shfl_xor_sync(0xffffffffu, rs1, 2);
    if (tg == 0) {
        atomicAdd(&sSum[rl0], rs0);
        atomicAdd(&sSum[rl1], rs1);
    }
    __syncthreads();
    if (t < 64) g_rowsum[(size_t)bh * SQ + q0 + t] = sSum[t];
}

// ================= Kernel 2: attn = (h+l)*inv (write), out = P'V * inv =================
// 64 q-rows/CTA, 256 thr (4 M x 2 D warps), j-tiles of 64, cp.async double-buffer.
// buffer: PH | PL | VH | VL, each 64 x PQ_B
#define O_PH 0
#define O_PL (64 * PQ_B)
#define O_VH (2 * 64 * PQ_B)
#define O_VL (3 * 64 * PQ_B)
#define K2_BSZ (4 * 64 * PQ_B)                // 36864
#define K2_INV (2 * K2_BSZ)                   // 73728
#define K2_SMEM (K2_INV + 256)

__global__ void __launch_bounds__(256, 2)
k2_pv(float* __restrict__ attn, float* __restrict__ out)
{
    extern __shared__ char sm[];
    float* sInv = (float*)(sm + K2_INV);

    const int t = threadIdx.x;
    const int lane = t & 31, w = t >> 5;
    const int g = lane >> 2, tg = lane & 3;
    const int wm = w >> 1, wn = w & 1;

    const int h  = blockIdx.y;
    const int b  = blockIdx.z;
    const int q0 = blockIdx.x * 64;
    const int bh = b * NH + h;

    float* ag = attn + ((size_t)bh * SQ + q0) * SQ;
    float* og = out  + ((size_t)bh * SQ + q0) * DH;
    const size_t vbase = (size_t)bh * SQ * DH;
    const size_t pbase = ((size_t)bh * SQ + q0) * SQ;

    if (t < 64) sInv[t] = 1.0f / g_rowsum[(size_t)bh * SQ + q0 + t];

    // stage tile 0: 2048 chunks (PH,PL,VH,VL x 64 rows x 8)
    {
        char* bufp = sm;
        #pragma unroll
        for (int i = 0; i < 8; ++i) {
            int lin = i * 256 + t;
            int plane = lin >> 9, row = (lin >> 3) & 63, c = lin & 7;
            const unsigned short* src =
                (plane == 0) ? gPh + pbase + (size_t)row * SQ + c * 8 :
                (plane == 1) ? gPl + pbase + (size_t)row * SQ + c * 8 :
                (plane == 2) ? gVh + vbase + (size_t)row * DH + c * 8 :
                               gVl + vbase + (size_t)row * DH + c * 8;
            cp16(smem_u32(bufp + plane * (64 * PQ_B) + row * PQ_B + c * 16), src);
        }
        CP_COMMIT;
    }

    const int aRow = wm * 16 + (lane & 15);
    const int aCol = ((lane >> 4) << 3);
    const int vRow = lane & 15;
    const int vCol = ((lane >> 4) << 4);

    float acc[4][4];
    #pragma unroll
    for (int nt = 0; nt < 4; ++nt)
        acc[nt][0] = acc[nt][1] = acc[nt][2] = acc[nt][3] = 0.0f;

    for (int jt = 0; jt < 32; ++jt) {
        __syncthreads();     // prior tile fully consumed
        if (jt < 31) {
            char* bufp = sm + ((jt + 1) & 1) * K2_BSZ;
            int jn = (jt + 1) * 64;
            #pragma unroll
            for (int i = 0; i < 8; ++i) {
                int lin = i * 256 + t;
                int plane = lin >> 9, row = (lin >> 3) & 63, c = lin & 7;
                const unsigned short* src =
                    (plane == 0) ? gPh + pbase + (size_t)row * SQ + jn + c * 8 :
                    (plane == 1) ? gPl + pbase + (size_t)row * SQ + jn + c * 8 :
                    (plane == 2) ? gVh + vbase + (size_t)(jn + row) * DH + c * 8 :
                                   gVl + vbase + (size_t)(jn + row) * DH + c * 8;
                cp16(smem_u32(bufp + plane * (64 * PQ_B) + row * PQ_B + c * 16), src);
            }
            CP_COMMIT;
            CP_WAIT1;
        } else {
            CP_WAIT0;
        }
        __syncthreads();     // tile jt staged

        const char* BUF = sm + (jt & 1) * K2_BSZ;

        // MMA: A = p' (m=q rows, k=j), B = V^T
        #pragma unroll
        for (int kc = 0; kc < 4; ++kc) {
            uint32_t Ah[4], Al[4];
            int aoff = aRow * PQ_B + (kc * 16 + aCol) * 2;
            ldsm_x4(smem_u32(BUF + O_PH + aoff), Ah);
            ldsm_x4(smem_u32(BUF + O_PL + aoff), Al);

            #pragma unroll
            for (int np = 0; np < 2; ++np) {
                uint32_t Bh[4], Bl[4];
                int voff = (kc * 16 + vRow) * PQ_B + (wn * 32 + np * 16) * 2 + vCol;
                ldsm_x4t(smem_u32(BUF + O_VH + voff), Bh);
                ldsm_x4t(smem_u32(BUF + O_VL + voff), Bl);
                mma_bf16(acc[np * 2],     Ah, Bh);
                mma_bf16(acc[np * 2],     Ah, Bl);
                mma_bf16(acc[np * 2],     Al, Bh);
                mma_bf16(acc[np * 2 + 1], Ah, Bh + 2);
                mma_bf16(acc[np * 2 + 1], Ah, Bl + 2);
                mma_bf16(acc[np * 2 + 1], Al, Bh + 2);
            }
        }

        // attn epilogue: (h+l)*inv from staged planes -> gmem
        #pragma unroll
        for (int i = 0; i < 4; ++i) {
            int lin = i * 256 + t;
            int row = lin >> 4, jg = lin & 15;
            uint2 H = *(const uint2*)(BUF + O_PH + row * PQ_B + jg * 8);
            uint2 L = *(const uint2*)(BUF + O_PL + row * PQ_B + jg * 8);
            float2 h01 = unpack2(H.x), h23 = unpack2(H.y);
            float2 l01 = unpack2(L.x), l23 = unpack2(L.y);
            float iv = sInv[row];
            float4 o;
            o.x = (h01.x + l01.x) * iv;
            o.y = (h01.y + l01.y) * iv;
            o.z = (h23.x + l23.x) * iv;
            o.w = (h23.y + l23.y) * iv;
            *(float4*)&ag[(size_t)row * SQ + jt * 64 + jg * 4] = o;
        }
    }

    // out epilogue: scale by inv[row]
    const int rl0 = wm * 16 + g, rl1 = rl0 + 8;
    const float iv0 = sInv[rl0], iv1 = sInv[rl1];
    #pragma unroll
    for (int nt = 0; nt < 4; ++nt) {
        int dc = wn * 32 + nt * 8 + 2 * tg;
        *(float2*)&og[rl0 * DH + dc] = make_float2(acc[nt][0] * iv0, acc[nt][1] * iv0);
        *(float2*)&og[rl1 * DH + dc] = make_float2(acc[nt][2] * iv1, acc[nt][3] * iv1);
    }
}

// ---------------- launch ----------------

extern "C" void kernel_launch(void* const* d_in, const int* in_sizes, int n_in,
                              void* d_out, int out_size)
{
    const float* q    = (const float*)d_in[0];
    const float* k    = (const float*)d_in[1];
    const float* v    = (const float*)d_in[2];
    const int*   mask = (const int*)d_in[3];

    float* out  = (float*)d_out;
    float* attn = out + (size_t)NB * NH * SQ * DH;   // tuple order: (output, attn)

    cudaFuncSetAttribute(k1_qk, cudaFuncAttributeMaxDynamicSharedMemorySize, K1_SMEM);
    cudaFuncSetAttribute(k2_pv, cudaFuncAttributeMaxDynamicSharedMemorySize, K2_SMEM);

    prep<<<3 * (N_ELEM / 4) / 256, 256>>>(q, k, v);
    prep_mask<<<NB * SQ * 64 / 256, 256>>>(mask);
    dim3 grid(SQ / 64, NH, NB);
    k1_qk<<<grid, 256, K1_SMEM>>>();
    k2_pv<<<grid, 256, K2_SMEM>>>(attn, out);
}

// round 16
// speedup vs baseline: 1.0744x; 1.0744x over previous
#include <cuda_runtime.h>
#include <cuda_bf16.h>
#include <stdint.h>

#define SQ 2048
#define DH 64
#define NH 16
#define NB 2
#define INV_T 0.125f
#define N_ELEM (NB * NH * SQ * DH)        // 4194304
#define N_ATTN ((size_t)NB * NH * SQ * SQ) // 134217728

__device__ float g_rowsum[NB * NH * SQ];
// pre-split bf16 hi/lo planes for Q/K/V
__device__ unsigned short gQh[N_ELEM], gQl[N_ELEM];
__device__ unsigned short gKh[N_ELEM], gKl[N_ELEM];
__device__ unsigned short gVh[N_ELEM], gVl[N_ELEM];
// p' planes (bf16 hi/lo)
__device__ unsigned short gPh[N_ATTN], gPl[N_ATTN];
// bit-packed mask: [B][S][64 words]
__device__ uint32_t g_mbits[NB * SQ * 64];

// ---------------- PTX helpers ----------------

__device__ __forceinline__ uint32_t smem_u32(const void* p) {
    return (uint32_t)__cvta_generic_to_shared(p);
}
__device__ __forceinline__ void ldsm_x4(uint32_t addr, uint32_t* r) {
    asm volatile("ldmatrix.sync.aligned.m8n8.x4.shared.b16 {%0,%1,%2,%3}, [%4];"
                 : "=r"(r[0]), "=r"(r[1]), "=r"(r[2]), "=r"(r[3]) : "r"(addr));
}
__device__ __forceinline__ void ldsm_x4t(uint32_t addr, uint32_t* r) {
    asm volatile("ldmatrix.sync.aligned.m8n8.x4.trans.shared.b16 {%0,%1,%2,%3}, [%4];"
                 : "=r"(r[0]), "=r"(r[1]), "=r"(r[2]), "=r"(r[3]) : "r"(addr));
}
__device__ __forceinline__ void mma_bf16(float* c, const uint32_t* a, const uint32_t* b) {
    asm volatile(
        "mma.sync.aligned.m16n8k16.row.col.f32.bf16.bf16.f32 "
        "{%0,%1,%2,%3}, {%4,%5,%6,%7}, {%8,%9}, {%0,%1,%2,%3};"
        : "+f"(c[0]), "+f"(c[1]), "+f"(c[2]), "+f"(c[3])
        : "r"(a[0]), "r"(a[1]), "r"(a[2]), "r"(a[3]), "r"(b[0]), "r"(b[1]));
}
__device__ __forceinline__ void cp16(uint32_t s, const void* g) {
    asm volatile("cp.async.cg.shared.global [%0], [%1], 16;" :: "r"(s), "l"(g));
}
#define CP_COMMIT asm volatile("cp.async.commit_group;")
#define CP_WAIT1  asm volatile("cp.async.wait_group 1;")
#define CP_WAIT0  asm volatile("cp.async.wait_group 0;")

__device__ __forceinline__ void split_bf(float x, uint16_t& h, uint16_t& l) {
    __nv_bfloat16 bh = __float2bfloat16(x);
    float r = x - __bfloat162float(bh);
    __nv_bfloat16 bl = __float2bfloat16(r);
    h = __bfloat16_as_ushort(bh);
    l = __bfloat16_as_ushort(bl);
}
__device__ __forceinline__ uint32_t pack2(uint16_t a, uint16_t b) {
    return (uint32_t)a | ((uint32_t)b << 16);
}
__device__ __forceinline__ float2 unpack2(uint32_t u) {
    __nv_bfloat162 b = *reinterpret_cast<__nv_bfloat162*>(&u);
    return __bfloat1622float2(b);
}
// packed split of a pair: Hp = bf16x2(e0,e1), Lp = bf16x2 of residuals
__device__ __forceinline__ void pack_split2(float e0, float e1, uint32_t& Hp, uint32_t& Lp) {
    asm("cvt.rn.bf16x2.f32 %0, %1, %2;" : "=r"(Hp) : "f"(e1), "f"(e0));
    float2 hf = unpack2(Hp);
    float r0 = e0 - hf.x, r1 = e1 - hf.y;
    asm("cvt.rn.bf16x2.f32 %0, %1, %2;" : "=r"(Lp) : "f"(r1), "f"(r0));
}

// ================= prep kernels =================

__global__ void __launch_bounds__(256)
prep(const float* __restrict__ q, const float* __restrict__ k, const float* __restrict__ v)
{
    int id = blockIdx.x * 256 + threadIdx.x;          // 0 .. 3*N/4-1
    int tsel = id / (N_ELEM / 4);
    int i4   = id % (N_ELEM / 4);
    const float* src = (tsel == 0) ? q : (tsel == 1) ? k : v;
    unsigned short* dh = (tsel == 0) ? gQh : (tsel == 1) ? gKh : gVh;
    unsigned short* dl = (tsel == 0) ? gQl : (tsel == 1) ? gKl : gVl;

    float4 f = ((const float4*)src)[i4];
    uint16_t h0, l0, h1, l1, h2, l2, h3, l3;
    split_bf(f.x, h0, l0); split_bf(f.y, h1, l1);
    split_bf(f.z, h2, l2); split_bf(f.w, h3, l3);
    uint2 H; H.x = pack2(h0, h1); H.y = pack2(h2, h3);
    uint2 L; L.x = pack2(l0, l1); L.y = pack2(l2, l3);
    ((uint2*)dh)[i4] = H;
    ((uint2*)dl)[i4] = L;
}

__global__ void __launch_bounds__(256)
prep_mask(const int* __restrict__ mask)
{
    int wid = blockIdx.x * 256 + threadIdx.x;         // word index 0..NB*SQ*64-1
    const int4* src = (const int4*)(mask + (size_t)wid * 32);
    uint32_t bits = 0;
    #pragma unroll
    for (int c = 0; c < 8; ++c) {
        int4 m = src[c];
        bits |= (m.x ? 1u : 0u) << (c * 4 + 0);
        bits |= (m.y ? 1u : 0u) << (c * 4 + 1);
        bits |= (m.z ? 1u : 0u) << (c * 4 + 2);
        bits |= (m.w ? 1u : 0u) << (c * 4 + 3);
    }
    g_mbits[wid] = bits;
}

// ================= Kernel 1: p' planes = split(exp(mask(QK^T/T))), row sums =================
// 64 q-rows/CTA, 256 thr (4 M x 2 N warps), j-tiles of 128, cp.async double-buffer.
#define PQ_B 144                               // 72 bf16 pitch (bytes)
#define K1_QH 0
#define K1_QL (64 * PQ_B)                      // 9216
#define K1_KBUF 18432                          // 2 buffers of (KH+KL) = 36864 each
#define K1_KSZ  36864
#define K1_SUM (K1_KBUF + 2 * K1_KSZ)          // 92160
#define K1_SMEM (K1_SUM + 256)

__global__ void __launch_bounds__(256, 2)
k1_qk()
{
    extern __shared__ char sm[];
    float* sSum = (float*)(sm + K1_SUM);

    const int t = threadIdx.x;
    const int lane = t & 31, w = t >> 5;
    const int g = lane >> 2, tg = lane & 3;
    const int wm = w >> 1, wn = w & 1;

    const int h  = blockIdx.y;
    const int b  = blockIdx.z;
    const int q0 = blockIdx.x * 64;
    const int bh = b * NH + h;

    const size_t qbase = ((size_t)bh * SQ + q0) * DH;   // ushort index
    const size_t kbase = (size_t)bh * SQ * DH;
    const size_t pbase = ((size_t)bh * SQ + q0) * SQ;

    // prologue: stage Q planes + K tile 0
    #pragma unroll
    for (int i = 0; i < 4; ++i) {
        int lin = i * 256 + t;
        int plane = lin >> 9, row = (lin >> 3) & 63, c = lin & 7;
        const unsigned short* src = (plane ? gQl : gQh) + qbase + (size_t)row * DH + c * 8;
        cp16(smem_u32(sm + (plane ? K1_QL : K1_QH) + row * PQ_B + c * 16), src);
    }
    #pragma unroll
    for (int i = 0; i < 8; ++i) {
        int lin = i * 256 + t;
        int plane = lin >> 10, row = (lin >> 3) & 127, c = lin & 7;
        const unsigned short* src = (plane ? gKl : gKh) + kbase + (size_t)row * DH + c * 8;
        cp16(smem_u32(sm + K1_KBUF + plane * (K1_KSZ / 2) + row * PQ_B + c * 16), src);
    }
    CP_COMMIT;
    if (t < 64) sSum[t] = 0.0f;

    const int aRow = wm * 16 + (lane & 15);
    const int aCol = ((lane >> 4) << 3);
    const int bRow = ((lane >> 4) << 3) + (lane & 7);
    const int bCol = ((lane >> 3) & 1) << 3;
    const int rl0 = wm * 16 + g, rl1 = rl0 + 8;
    float rs0 = 0.0f, rs1 = 0.0f;

    const uint32_t* mb0 = &g_mbits[((size_t)b * SQ + q0 + rl0) * 64];
    const uint32_t* mb1 = &g_mbits[((size_t)b * SQ + q0 + rl1) * 64];

    for (int jt = 0; jt < 16; ++jt) {
        __syncthreads();
        if (jt < 15) {
            char* kb = sm + K1_KBUF + ((jt + 1) & 1) * K1_KSZ;
            size_t kt = kbase + (size_t)(jt + 1) * 128 * DH;
            #pragma unroll
            for (int i = 0; i < 8; ++i) {
                int lin = i * 256 + t;
                int plane = lin >> 10, row = (lin >> 3) & 127, c = lin & 7;
                const unsigned short* src = (plane ? gKl : gKh) + kt + (size_t)row * DH + c * 8;
                cp16(smem_u32(kb + plane * (K1_KSZ / 2) + row * PQ_B + c * 16), src);
            }
            CP_COMMIT;
            CP_WAIT1;
        } else {
            CP_WAIT0;
        }
        __syncthreads();

        const char* KB = sm + K1_KBUF + (jt & 1) * K1_KSZ;

        float acc[8][4];
        #pragma unroll
        for (int nt = 0; nt < 8; ++nt)
            acc[nt][0] = acc[nt][1] = acc[nt][2] = acc[nt][3] = 0.0f;

        #pragma unroll
        for (int kc = 0; kc < 4; ++kc) {
            uint32_t Ah[4], Al[4];
            int aoff = aRow * PQ_B + (kc * 16 + aCol) * 2;
            ldsm_x4(smem_u32(sm + K1_QH + aoff), Ah);
            ldsm_x4(smem_u32(sm + K1_QL + aoff), Al);

            #pragma unroll
            for (int np = 0; np < 4; ++np) {
                uint32_t Bh[4], Bl[4];
                int boff = (wn * 64 + np * 16 + bRow) * PQ_B + (kc * 16 + bCol) * 2;
                ldsm_x4(smem_u32(KB + boff), Bh);
                ldsm_x4(smem_u32(KB + (K1_KSZ / 2) + boff), Bl);
                mma_bf16(acc[np * 2],     Ah, Bh);
                mma_bf16(acc[np * 2],     Ah, Bl);
                mma_bf16(acc[np * 2],     Al, Bh);
                mma_bf16(acc[np * 2 + 1], Ah, Bh + 2);
                mma_bf16(acc[np * 2 + 1], Ah, Bl + 2);
                mma_bf16(acc[np * 2 + 1], Al, Bh + 2);
            }
        }

        // epilogue: mask bits, exp, packed split, pair-shuffle, 8B plane stores, rowsums
        const uint2 mw0 = *(const uint2*)&mb0[jt * 4 + wn * 2];
        const uint2 mw1 = *(const uint2*)&mb1[jt * 4 + wn * 2];
        #pragma unroll
        for (int nt = 0; nt < 8; ++nt) {
            int sh = (nt & 3) * 8 + 2 * tg;
            uint32_t w0 = (nt < 4) ? mw0.x : mw0.y;
            uint32_t w1 = (nt < 4) ? mw1.x : mw1.y;
            float e00 = ((w0 >> sh) & 1)       ? __expf(acc[nt][0] * INV_T) : 0.0f;
            float e01 = ((w0 >> (sh + 1)) & 1) ? __expf(acc[nt][1] * INV_T) : 0.0f;
            float e10 = ((w1 >> sh) & 1)       ? __expf(acc[nt][2] * INV_T) : 0.0f;
            float e11 = ((w1 >> (sh + 1)) & 1) ? __expf(acc[nt][3] * INV_T) : 0.0f;
            rs0 += e00 + e01;
            rs1 += e10 + e11;

            uint32_t Hp0, Lp0, Hp1, Lp1;
            pack_split2(e00, e01, Hp0, Lp0);
            pack_split2(e10, e11, Hp1, Lp1);
            uint32_t oH0 = __shfl_xor_sync(0xffffffffu, Hp0, 1);
            uint32_t oL0 = __shfl_xor_sync(0xffffffffu, Lp0, 1);
            uint32_t oH1 = __shfl_xor_sync(0xffffffffu, Hp1, 1);
            uint32_t oL1 = __shfl_xor_sync(0xffffffffu, Lp1, 1);

            // even tg lanes own hi-plane 4-wide, odd lanes lo-plane 4-wide
            int j0 = jt * 128 + wn * 64 + nt * 8 + (tg & 2) * 2;
            if ((tg & 1) == 0) {
                uint2 s0; s0.x = Hp0; s0.y = oH0;
                uint2 s1; s1.x = Hp1; s1.y = oH1;
                *(uint2*)&gPh[pbase + (size_t)rl0 * SQ + j0] = s0;
                *(uint2*)&gPh[pbase + (size_t)rl1 * SQ + j0] = s1;
            } else {
                uint2 s0; s0.x = oL0; s0.y = Lp0;
                uint2 s1; s1.x = oL1; s1.y = Lp1;
                *(uint2*)&gPl[pbase + (size_t)rl0 * SQ + j0] = s0;
                *(uint2*)&gPl[pbase + (size_t)rl1 * SQ + j0] = s1;
            }
        }
    }

    rs0 += __shfl_xor_sync(0xffffffffu, rs0, 1);
    rs0 += __shfl_xor_sync(0xffffffffu, rs0, 2);
    rs1 += __shfl_xor_sync(0xffffffffu, rs1, 1);
    rs1 += __shfl_xor_sync(0xffffffffu, rs1, 2);
    if (tg == 0) {
        atomicAdd(&sSum[rl0], rs0);
        atomicAdd(&sSum[rl1], rs1);
    }
    __syncthreads();
    if (t < 64) g_rowsum[(size_t)bh * SQ + q0 + t] = sSum[t];
}

// ================= Kernel 2: attn = (h+l)*inv (write), out = P'V * inv =================
// 64 q-rows/CTA, 256 thr (4 M x 2 D warps), j-tiles of 64, cp.async double-buffer.
// buffer: PH | PL | VH | VL, each 64 x PQ_B
#define O_PH 0
#define O_PL (64 * PQ_B)
#define O_VH (2 * 64 * PQ_B)
#define O_VL (3 * 64 * PQ_B)
#define K2_BSZ (4 * 64 * PQ_B)                // 36864
#define K2_INV (2 * K2_BSZ)                   // 73728
#define K2_SMEM (K2_INV + 256)

__global__ void __launch_bounds__(256, 2)
k2_pv(float* __restrict__ attn, float* __restrict__ out)
{
    extern __shared__ char sm[];
    float* sInv = (float*)(sm + K2_INV);

    const int t = threadIdx.x;
    const int lane = t & 31, w = t >> 5;
    const int g = lane >> 2, tg = lane & 3;
    const int wm = w >> 1, wn = w & 1;

    const int h  = blockIdx.y;
    const int b  = blockIdx.z;
    const int q0 = blockIdx.x * 64;
    const int bh = b * NH + h;

    float* ag = attn + ((size_t)bh * SQ + q0) * SQ;
    float* og = out  + ((size_t)bh * SQ + q0) * DH;
    const size_t vbase = (size_t)bh * SQ * DH;
    const size_t pbase = ((size_t)bh * SQ + q0) * SQ;

    if (t < 64) sInv[t] = 1.0f / g_rowsum[(size_t)bh * SQ + q0 + t];

    // stage tile 0: 2048 chunks (PH,PL,VH,VL x 64 rows x 8)
    {
        char* bufp = sm;
        #pragma unroll
        for (int i = 0; i < 8; ++i) {
            int lin = i * 256 + t;
            int plane = lin >> 9, row = (lin >> 3) & 63, c = lin & 7;
            const unsigned short* src =
                (plane == 0) ? gPh + pbase + (size_t)row * SQ + c * 8 :
                (plane == 1) ? gPl + pbase + (size_t)row * SQ + c * 8 :
                (plane == 2) ? gVh + vbase + (size_t)row * DH + c * 8 :
                               gVl + vbase + (size_t)row * DH + c * 8;
            cp16(smem_u32(bufp + plane * (64 * PQ_B) + row * PQ_B + c * 16), src);
        }
        CP_COMMIT;
    }

    const int aRow = wm * 16 + (lane & 15);
    const int aCol = ((lane >> 4) << 3);
    const int vRow = lane & 15;
    const int vCol = ((lane >> 4) << 4);

    float acc[4][4];
    #pragma unroll
    for (int nt = 0; nt < 4; ++nt)
        acc[nt][0] = acc[nt][1] = acc[nt][2] = acc[nt][3] = 0.0f;

    for (int jt = 0; jt < 32; ++jt) {
        __syncthreads();     // prior tile fully consumed
        if (jt < 31) {
            char* bufp = sm + ((jt + 1) & 1) * K2_BSZ;
            int jn = (jt + 1) * 64;
            #pragma unroll
            for (int i = 0; i < 8; ++i) {
                int lin = i * 256 + t;
                int plane = lin >> 9, row = (lin >> 3) & 63, c = lin & 7;
                const unsigned short* src =
                    (plane == 0) ? gPh + pbase + (size_t)row * SQ + jn + c * 8 :
                    (plane == 1) ? gPl + pbase + (size_t)row * SQ + jn + c * 8 :
                    (plane == 2) ? gVh + vbase + (size_t)(jn + row) * DH + c * 8 :
                                   gVl + vbase + (size_t)(jn + row) * DH + c * 8;
                cp16(smem_u32(bufp + plane * (64 * PQ_B) + row * PQ_B + c * 16), src);
            }
            CP_COMMIT;
            CP_WAIT1;
        } else {
            CP_WAIT0;
        }
        __syncthreads();     // tile jt staged

        const char* BUF = sm + (jt & 1) * K2_BSZ;

        // MMA: A = p' (m=q rows, k=j), B = V^T
        #pragma unroll
        for (int kc = 0; kc < 4; ++kc) {
            uint32_t Ah[4], Al[4];
            int aoff = aRow * PQ_B + (kc * 16 + aCol) * 2;
            ldsm_x4(smem_u32(BUF + O_PH + aoff), Ah);
            ldsm_x4(smem_u32(BUF + O_PL + aoff), Al);

            #pragma unroll
            for (int np = 0; np < 2; ++np) {
                uint32_t Bh[4], Bl[4];
                int voff = (kc * 16 + vRow) * PQ_B + (wn * 32 + np * 16) * 2 + vCol;
                ldsm_x4t(smem_u32(BUF + O_VH + voff), Bh);
                ldsm_x4t(smem_u32(BUF + O_VL + voff), Bl);
                mma_bf16(acc[np * 2],     Ah, Bh);
                mma_bf16(acc[np * 2],     Ah, Bl);
                mma_bf16(acc[np * 2],     Al, Bh);
                mma_bf16(acc[np * 2 + 1], Ah, Bh + 2);
                mma_bf16(acc[np * 2 + 1], Ah, Bl + 2);
                mma_bf16(acc[np * 2 + 1], Al, Bh + 2);
            }
        }

        // attn epilogue: (h+l)*inv from staged planes -> gmem
        #pragma unroll
        for (int i = 0; i < 4; ++i) {
            int lin = i * 256 + t;
            int row = lin >> 4, jg = lin & 15;
            uint2 H = *(const uint2*)(BUF + O_PH + row * PQ_B + jg * 8);
            uint2 L = *(const uint2*)(BUF + O_PL + row * PQ_B + jg * 8);
            float2 h01 = unpack2(H.x), h23 = unpack2(H.y);
            float2 l01 = unpack2(L.x), l23 = unpack2(L.y);
            float iv = sInv[row];
            float4 o;
            o.x = (h01.x + l01.x) * iv;
            o.y = (h01.y + l01.y) * iv;
            o.z = (h23.x + l23.x) * iv;
            o.w = (h23.y + l23.y) * iv;
            *(float4*)&ag[(size_t)row * SQ + jt * 64 + jg * 4] = o;
        }
    }

    // out epilogue: scale by inv[row]
    const int rl0 = wm * 16 + g, rl1 = rl0 + 8;
    const float iv0 = sInv[rl0], iv1 = sInv[rl1];
    #pragma unroll
    for (int nt = 0; nt < 4; ++nt) {
        int dc = wn * 32 + nt * 8 + 2 * tg;
        *(float2*)&og[rl0 * DH + dc] = make_float2(acc[nt][0] * iv0, acc[nt][1] * iv0);
        *(float2*)&og[rl1 * DH + dc] = make_float2(acc[nt][2] * iv1, acc[nt][3] * iv1);
    }
}

// ---------------- launch ----------------

extern "C" void kernel_launch(void* const* d_in, const int* in_sizes, int n_in,
                              void* d_out, int out_size)
{
    const float* q    = (const float*)d_in[0];
    const float* k    = (const float*)d_in[1];
    const float* v    = (const float*)d_in[2];
    const int*   mask = (const int*)d_in[3];

    float* out  = (float*)d_out;
    float* attn = out + (size_t)NB * NH * SQ * DH;   // tuple order: (output, attn)

    cudaFuncSetAttribute(k1_qk, cudaFuncAttributeMaxDynamicSharedMemorySize, K1_SMEM);
    cudaFuncSetAttribute(k2_pv, cudaFuncAttributeMaxDynamicSharedMemorySize, K2_SMEM);

    prep<<<3 * (N_ELEM / 4) / 256, 256>>>(q, k, v);
    prep_mask<<<NB * SQ * 64 / 256, 256>>>(mask);
    dim3 grid(SQ / 64, NH, NB);
    k1_qk<<<grid, 256, K1_SMEM>>>();
    k2_pv<<<grid, 256, K2_SMEM>>>(attn, out);
}